// round 10
// baseline (speedup 1.0000x reference)
#include <cuda_runtime.h>
#include <cstdint>

#define BATCH    512
#define BITD     64
#define NCLS     100
#define NTRAIN   100000
#define MARGIN_F 128.0f

#define BATCH_BLOCKS 128         // 4 rows per block
#define SCAN_BLOCKS  391         // ceil(100000/256)
#define UST_BLOCKS   512
#define FIX_BLOCKS   128         // 4 batch rows per block
#define MEGA_BLOCKS  (SCAN_BLOCKS + UST_BLOCKS + FIX_BLOCKS)

#define Y_U4_TOTAL   (NTRAIN * 25)      // Y as uint4: 25 per row (400B rows)

// -------- device accumulators / scratch (no allocations allowed) --------
__device__ double   g_SUsq;           // sum_n |U'_n|^2 (ust + fix deltas)
__device__ double   g_corr;           // hinge corrections over mismatch pairs
__device__ double   g_SUpad[BITD * 16]; // padded col sums (1 dbl / 128B line)
__device__ float    g_usq[BATCH];     // per-row |u_b|^2
__device__ __align__(16) unsigned g_ypk[4 * BATCH];   // packed labels [word][row]
__device__ __align__(16) float g_supart[BATCH_BLOCKS * BITD]; // u col partials
__device__ float    g_uqpart[BATCH_BLOCKS];  // per-block sum |u|^2 partials
__device__ float    g_s2part[BATCH_BLOCKS];  // per-block s2 partials
__device__ unsigned g_done;           // mega-block completion counter

__device__ __forceinline__ float wred(float v) {
#pragma unroll
    for (int o = 16; o; o >>= 1) v += __shfl_xor_sync(0xffffffffu, v, o);
    return v;
}
__device__ __forceinline__ double wredd(double v) {
#pragma unroll
    for (int o = 16; o; o >>= 1) v += __shfl_xor_sync(0xffffffffu, v, o);
    return v;
}

// --------- rare path: exact pair term 0.5*(max(m-d,0) - d) --------------
// Serial FMA chain: identical FP-op order wherever compiled -> the
// add-then-subtract cancellation across scan/fix roles is bit-exact.
__device__ __noinline__ double pair_term(int b, const float* __restrict__ ur,
                                         const float* __restrict__ vr) {
    float dot = 0.f, vsq = 0.f;
#pragma unroll 16
    for (int k = 0; k < BITD; k++) {
        float a = ur[k], c = vr[k];
        dot = fmaf(a, c, dot);
        vsq = fmaf(c, c, vsq);
    }
    float d = g_usq[b] - 2.f * dot + vsq;
    d = fmaxf(d, 0.f);
    return 0.5 * ((double)fmaxf(MARGIN_F - d, 0.f) - (double)d);
}

// Permuted pack mapping: class c -> word (c&3), bit (c>>2). Used identically
// everywhere; set intersection is permutation-invariant.
template<int Q>
__device__ __forceinline__ void pack25(const unsigned* __restrict__ sw,
                                       unsigned& p0, unsigned& p1,
                                       unsigned& p2, unsigned& p3) {
#pragma unroll
    for (int i = 0; i < 25; i++) {
        const int c = Q * 25 + i;                 // compile-time
        const unsigned m = 1u << (c >> 2);
        if (__uint_as_float(sw[i]) != 0.f) {
            switch (c & 3) {
            case 0: p0 |= m; break;
            case 1: p1 |= m; break;
            case 2: p2 |= m; break;
            case 3: p3 |= m; break;
            }
        }
    }
}

// warp-ballot pack (used for the few rows in k_batch / fix role)
__device__ __forceinline__ uint4 pack_ballots(const float* __restrict__ row,
                                              int lane) {
    float4 v = make_float4(0.f, 0.f, 0.f, 0.f);
    if (lane < 25) v = ((const float4*)row)[lane];
    uint4 r;
    r.x = __ballot_sync(0xffffffffu, v.x != 0.f);
    r.y = __ballot_sync(0xffffffffu, v.y != 0.f);
    r.z = __ballot_sync(0xffffffffu, v.z != 0.f);
    r.w = __ballot_sync(0xffffffffu, v.w != 0.f);
    return r;
}

// ------------- batch stats + y pack: 128 blocks, 4 rows per block --------
__global__ void __launch_bounds__(256)
k_batch(const float* __restrict__ u, const float* __restrict__ y) {
    __shared__ float scol[BITD];
    __shared__ float sv[8];
    int t    = threadIdx.x;
    int lane = t & 31, warp = t >> 5;
    int row  = blockIdx.x * 4 + warp;

    if (t < BITD) scol[t] = 0.f;
    if (blockIdx.x == 0) {
        if (t < BITD) g_SUpad[t * 16] = 0.0;
        if (t == 0) { g_SUsq = 0.0; g_corr = 0.0; g_done = 0u; }
    }
    __syncthreads();

    float2 v = ((const float2*)(u + row * BITD))[lane];
    float usq = v.x * v.x + v.y * v.y;
    float s2  = ((v.x > 0.f) ? 0.f : ((v.x < 0.f) ? 2.f : 1.f))
              + ((v.y > 0.f) ? 0.f : ((v.y < 0.f) ? 2.f : 1.f));
    atomicAdd(&scol[2 * lane],     v.x);
    atomicAdd(&scol[2 * lane + 1], v.y);
    float usqr = wred(usq);
    float s2r  = wred(s2);
    if (lane == 0) { g_usq[row] = usqr; sv[warp] = usqr; sv[4 + warp] = s2r; }

    uint4 b = pack_ballots(y + (size_t)row * NCLS, lane);
    if (lane == 0) {
        g_ypk[row]             = b.x;
        g_ypk[BATCH + row]     = b.y;
        g_ypk[2 * BATCH + row] = b.z;
        g_ypk[3 * BATCH + row] = b.w;
    }
    __syncthreads();

    if (t < BITD) g_supart[blockIdx.x * BITD + t] = scol[t];
    if (t == 0) {
        g_uqpart[blockIdx.x] = sv[0] + sv[1] + sv[2] + sv[3];
        g_s2part[blockIdx.x] = sv[4] + sv[5] + sv[6] + sv[7];
    }
}

// ------------- mega kernel: scan + U-stats + fix + finalize tail ---------
__global__ void __launch_bounds__(256, 8)
k_mega(const float* __restrict__ u, const int* __restrict__ ind,
       const float* __restrict__ U, const float* __restrict__ Y,
       float* __restrict__ out) {
    // carved buffer: scan staging (25.6KB) / fix (sind 2KB + table 8KB)
    __shared__ __align__(16) char sbuf[64 * 100 * 4];
    __shared__ unsigned spack[256 * 5];   // per-row packs, stride-5 padded
    __shared__ float    scol[BITD + 8];
    __shared__ unsigned yn4[4];
    __shared__ int      s_last;
    __shared__ int      s_flag;

    int t    = threadIdx.x;
    int lane = t & 31, warp = t >> 5;

    if (blockIdx.x < SCAN_BLOCKS) {
        // ================= scan role =====================================
        unsigned* stg = (unsigned*)sbuf;            // 6400 words
        const uint4* Y4 = (const uint4*)Y;
        int base4 = blockIdx.x * 6400;              // 256 rows * 25 uint4

        // ---- pack phase: 4 chunks of 64 rows, flat coalesced staging ----
#pragma unroll 1
        for (int ch = 0; ch < 4; ch++) {
#pragma unroll
            for (int j = 0; j < 7; j++) {
                int k = t + j * 256;
                if (k < 1600) {
                    int g = base4 + ch * 1600 + k;
                    if (g >= Y_U4_TOTAL) g = Y_U4_TOTAL - 1;
                    ((uint4*)stg)[k] = Y4[g];
                }
            }
            __syncthreads();

            // quarter-row pack from shared (stride-25: conflict-free)
            unsigned p0 = 0, p1 = 0, p2 = 0, p3 = 0;
            const unsigned* sw = stg + t * 25;
            switch (t & 3) {
            case 0: pack25<0>(sw, p0, p1, p2, p3); break;
            case 1: pack25<1>(sw, p0, p1, p2, p3); break;
            case 2: pack25<2>(sw, p0, p1, p2, p3); break;
            default: pack25<3>(sw, p0, p1, p2, p3); break;
            }
            p0 |= __shfl_xor_sync(0xffffffffu, p0, 1);
            p0 |= __shfl_xor_sync(0xffffffffu, p0, 2);
            p1 |= __shfl_xor_sync(0xffffffffu, p1, 1);
            p1 |= __shfl_xor_sync(0xffffffffu, p1, 2);
            p2 |= __shfl_xor_sync(0xffffffffu, p2, 1);
            p2 |= __shfl_xor_sync(0xffffffffu, p2, 2);
            p3 |= __shfl_xor_sync(0xffffffffu, p3, 1);
            p3 |= __shfl_xor_sync(0xffffffffu, p3, 2);
            if ((t & 3) == 0) {
                int grow = ch * 64 + (t >> 2);
                spack[grow * 5 + 0] = p0;
                spack[grow * 5 + 1] = p1;
                spack[grow * 5 + 2] = p2;
                spack[grow * 5 + 3] = p3;
            }
            __syncthreads();
        }

        // ---- stage batch pack table into (re-aliased) stg ----
        ((uint4*)stg)[t]       = ((const uint4*)g_ypk)[t];
        ((uint4*)stg)[t + 256] = ((const uint4*)g_ypk)[t + 256];
        __syncthreads();

        int n = blockIdx.x * 256 + t;
        unsigned w0 = spack[t * 5],     w1 = spack[t * 5 + 1];
        unsigned w2 = spack[t * 5 + 2], w3 = spack[t * 5 + 3];

        if (n < NTRAIN) {
            const unsigned* sh = stg;
            const uint4* sh4 = (const uint4*)stg;
            double corr = 0.0;
#pragma unroll 4
            for (int b0i = 0; b0i < BATCH; b0i += 8) {
                uint4 pa = sh4[b0i >> 2];
                uint4 pb = sh4[(b0i >> 2) + 1];
                unsigned mna = min(min(pa.x & w0, pa.y & w0),
                                   min(pa.z & w0, pa.w & w0));
                unsigned mnb = min(min(pb.x & w0, pb.y & w0),
                                   min(pb.z & w0, pb.w & w0));
                if (min(mna, mnb) == 0u) {
#pragma unroll 1
                    for (int j = 0; j < 8; j++) {
                        int b = b0i + j;
                        unsigned r = (sh[b] & w0) | (sh[BATCH + b] & w1) |
                                     (sh[2 * BATCH + b] & w2) |
                                     (sh[3 * BATCH + b] & w3);
                        if (r == 0u)
                            corr += pair_term(b, u + b * BITD,
                                              U + (size_t)n * BITD);
                    }
                }
            }
            if (corr != 0.0) atomicAdd(&g_corr, corr);
        }
    } else if (blockIdx.x < SCAN_BLOCKS + UST_BLOCKS) {
        // ================= U stats role ==================================
        const int nth = UST_BLOCKS * 256;                 // 131072
        int gid = (blockIdx.x - SCAN_BLOCKS) * 256 + t;
        const float4* U4 = (const float4*)U;
        const int total4 = NTRAIN * BITD / 4;             // 1.6M

        float c0 = 0.f, c1 = 0.f, c2 = 0.f, c3 = 0.f, sq = 0.f;
#pragma unroll 4
        for (int i = gid; i < total4; i += nth) {
            float4 v = U4[i];
            c0 += v.x; c1 += v.y; c2 += v.z; c3 += v.w;
            sq += v.x * v.x + v.y * v.y + v.z * v.z + v.w * v.w;
        }
        int cbase = (4 * gid) & (BITD - 1);
        c0 += __shfl_xor_sync(0xffffffffu, c0, 16);
        c1 += __shfl_xor_sync(0xffffffffu, c1, 16);
        c2 += __shfl_xor_sync(0xffffffffu, c2, 16);
        c3 += __shfl_xor_sync(0xffffffffu, c3, 16);
        sq = wred(sq);

        if (t < BITD + 8) scol[t] = 0.f;
        __syncthreads();
        if (lane < 16) {
            atomicAdd(&scol[cbase],     c0);
            atomicAdd(&scol[cbase + 1], c1);
            atomicAdd(&scol[cbase + 2], c2);
            atomicAdd(&scol[cbase + 3], c3);
        }
        if (lane == 0) scol[BITD + warp] = sq;
        __syncthreads();
        if (t < BITD) atomicAdd(&g_SUpad[t * 16], (double)scol[t]);
        if (t == 0) {
            float s = 0.f;
#pragma unroll
            for (int w = 0; w < 8; w++) s += scol[BITD + w];
            atomicAdd(&g_SUsq, (double)s);
        }
    } else {
        // ============ fix role: 4 batch rows per block ===================
        int i0 = (blockIdx.x - SCAN_BLOCKS - UST_BLOCKS) * 4;   // 0..508
        int*      sind = (int*)sbuf;                 // 2KB
        unsigned* sht  = (unsigned*)(sbuf + 2048);   // 8KB table

        sind[t]       = ind[t];
        sind[t + 256] = ind[t + 256];
#pragma unroll
        for (int j = 0; j < 2; j++)
            ((uint4*)sht)[t + j * 256] = ((const uint4*)g_ypk)[t + j * 256];
        __syncthreads();

#pragma unroll 1
        for (int ri = 0; ri < 4; ri++) {
            int i = i0 + ri;
            int n = sind[i];

            if (t == 0) s_last = 1;
            __syncthreads();
            for (int j = i + 1 + t; j < BATCH; j += 256)
                if (sind[j] == n) s_last = 0;
            __syncthreads();

            if (s_last) {
                if (warp == 0) {
                    uint4 b = pack_ballots(Y + (size_t)n * NCLS, lane);
                    if (lane == 0) { yn4[0] = b.x; yn4[1] = b.y;
                                     yn4[2] = b.z; yn4[3] = b.w; }
                }
                __syncthreads();

                unsigned yn0 = yn4[0], yn1 = yn4[1];
                unsigned yn2 = yn4[2], yn3 = yn4[3];
                unsigned m0 = sht[i],             m1 = sht[BATCH + i];
                unsigned m2 = sht[2 * BATCH + i], m3 = sht[3 * BATCH + i];
                double corr = 0.0;
#pragma unroll
                for (int bb = 0; bb < 2; bb++) {
                    int b = t + bb * 256;
                    unsigned ro = (sht[b] & yn0) | (sht[BATCH + b] & yn1) |
                                  (sht[2 * BATCH + b] & yn2) |
                                  (sht[3 * BATCH + b] & yn3);
                    if (ro == 0u)   // remove scan's old-data contribution
                        corr -= pair_term(b, u + b * BITD,
                                          U + (size_t)n * BITD);
                    unsigned rn = (sht[b] & m0) | (sht[BATCH + b] & m1) |
                                  (sht[2 * BATCH + b] & m2) |
                                  (sht[3 * BATCH + b] & m3);
                    if (rn == 0u)   // add updated-data contribution
                        corr += pair_term(b, u + b * BITD, u + i * BITD);
                }
                if (corr != 0.0) atomicAdd(&g_corr, corr);

                float dsq = 0.f;
                if (t < BITD) {
                    float a = u[i * BITD + t];
                    float c = U[(size_t)n * BITD + t];
                    atomicAdd(&g_SUpad[t * 16], (double)(a - c));
                    dsq = a * a - c * c;
                    dsq = wred(dsq);
                    if (lane == 0) atomicAdd(&g_SUsq, (double)dsq);
                }
            }
            __syncthreads();
        }
    }

    // ================= finalize tail: last block to finish ===============
    __threadfence();
    __syncthreads();
    if (t == 0)
        s_flag = (atomicAdd(&g_done, 1u) == MEGA_BLOCKS - 1) ? 1 : 0;
    __syncthreads();
    if (!s_flag) return;
    __threadfence();

    __shared__ double sterm[BITD];
    __shared__ double sparts[8];

    if (t < BITD) {
        double s = 0.0;
#pragma unroll 8
        for (int i = 0; i < BATCH_BLOCKS; i++)
            s += (double)g_supart[i * BITD + t];
        sterm[t] = s * g_SUpad[t * 16];
    }
    if (t < BATCH_BLOCKS) {
        double q = wredd((double)g_uqpart[t]);
        double a = wredd((double)g_s2part[t]);
        if (lane == 0) { sparts[warp] = q; sparts[4 + warp] = a; }
    }
    __syncthreads();

    if (t == 0) {
        double dotsum = 0.0;
#pragma unroll
        for (int k = 0; k < BITD; k++) dotsum += sterm[k];
        double sum_usq = sparts[0] + sparts[1] + sparts[2] + sparts[3];
        double s2sum   = sparts[4] + sparts[5] + sparts[6] + sparts[7];
        double sum_dist = (double)NTRAIN * sum_usq
                        + (double)BATCH  * g_SUsq
                        - 2.0 * dotsum;
        double loss1 = (0.5 * sum_dist + g_corr)
                     / ((double)BATCH * (double)NTRAIN);
        double loss2 = 0.1 * s2sum / ((double)BATCH * (double)BITD);
        out[0] = (float)(loss1 + loss2);
    }
}

// ------------------------------------------------------------ launcher
extern "C" void kernel_launch(void* const* d_in, const int* in_sizes, int n_in,
                              void* d_out, int out_size) {
    const float* u   = (const float*)d_in[0];   // [512, 64]
    const float* y   = (const float*)d_in[1];   // [512, 100]
    const int*   ind = (const int*)  d_in[2];   // [512]
    const float* U   = (const float*)d_in[3];   // [100000, 64]
    const float* Y   = (const float*)d_in[4];   // [100000, 100]
    float* out = (float*)d_out;

    k_batch<<<BATCH_BLOCKS, 256>>>(u, y);
    k_mega<<<MEGA_BLOCKS, 256>>>(u, ind, U, Y, out);
}

// round 11
// speedup vs baseline: 1.1937x; 1.1937x over previous
#include <cuda_runtime.h>
#include <cstdint>

#define BATCH    512
#define BITD     64
#define NCLS     100
#define NTRAIN   100000
#define MARGIN_F 128.0f

#define BATCH_BLOCKS 128         // k_batch: 4 rows per block
#define PACK_BLOCKS  782         // k_pack: 8 warps * 16 rows each
#define SCAN_BLOCKS  391         // ceil(100000/256)
#define UST_BLOCKS   512
#define FIX_BLOCKS   512         // 1 batch row per block
#define MEGA_BLOCKS  (SCAN_BLOCKS + UST_BLOCKS + FIX_BLOCKS)

// -------- device accumulators / scratch (no allocations allowed) --------
__device__ double   g_SUsq;           // sum_n |U'_n|^2 (ust + fix deltas)
__device__ double   g_corr;           // hinge corrections over mismatch pairs
__device__ double   g_SUpad[BITD * 16]; // padded col sums (1 dbl / 128B line)
__device__ float    g_usq[BATCH];     // per-row |u_b|^2
__device__ __align__(16) unsigned g_ypk[4 * BATCH];  // batch packs [word][row]
__device__ uint4    g_ypkN[NTRAIN];   // packed training labels, one uint4/row
__device__ __align__(16) float g_supart[BATCH_BLOCKS * BITD]; // u col partials
__device__ float    g_uqpart[BATCH_BLOCKS];  // per-block sum |u|^2 partials
__device__ float    g_s2part[BATCH_BLOCKS];  // per-block s2 partials
__device__ unsigned g_done;           // mega-block completion counter

__device__ __forceinline__ float wred(float v) {
#pragma unroll
    for (int o = 16; o; o >>= 1) v += __shfl_xor_sync(0xffffffffu, v, o);
    return v;
}
__device__ __forceinline__ double wredd(double v) {
#pragma unroll
    for (int o = 16; o; o >>= 1) v += __shfl_xor_sync(0xffffffffu, v, o);
    return v;
}

// --------- rare path: exact pair term 0.5*(max(m-d,0) - d) --------------
// Serial FMA chain: identical FP-op order wherever compiled -> the
// add-then-subtract cancellation across scan/fix roles is bit-exact.
__device__ __noinline__ double pair_term(int b, const float* __restrict__ ur,
                                         const float* __restrict__ vr) {
    float dot = 0.f, vsq = 0.f;
#pragma unroll 16
    for (int k = 0; k < BITD; k++) {
        float a = ur[k], c = vr[k];
        dot = fmaf(a, c, dot);
        vsq = fmaf(c, c, vsq);
    }
    float d = g_usq[b] - 2.f * dot + vsq;
    d = fmaxf(d, 0.f);
    return 0.5 * ((double)fmaxf(MARGIN_F - d, 0.f) - (double)d);
}

// Permuted pack (identical everywhere): lane l<25 covers classes 4l..4l+3;
// ballot word w gets bit l from class 4l+w, i.e. class c -> word (c&3),
// bit (c>>2). Set intersection is permutation-invariant.
__device__ __forceinline__ uint4 pack_ballots_v(float4 v) {
    uint4 r;
    r.x = __ballot_sync(0xffffffffu, v.x != 0.f);
    r.y = __ballot_sync(0xffffffffu, v.y != 0.f);
    r.z = __ballot_sync(0xffffffffu, v.z != 0.f);
    r.w = __ballot_sync(0xffffffffu, v.w != 0.f);
    return r;
}
__device__ __forceinline__ uint4 pack_ballots(const float* __restrict__ row,
                                              int lane) {
    float4 v = make_float4(0.f, 0.f, 0.f, 0.f);
    if (lane < 25) v = ((const float4*)row)[lane];
    return pack_ballots_v(v);
}

// ------------- batch stats + y pack: 128 blocks, 4 rows per block --------
__global__ void __launch_bounds__(256)
k_batch(const float* __restrict__ u, const float* __restrict__ y) {
    __shared__ float scol[BITD];
    __shared__ float sv[8];
    int t    = threadIdx.x;
    int lane = t & 31, warp = t >> 5;
    int row  = blockIdx.x * 4 + warp;

    if (t < BITD) scol[t] = 0.f;
    if (blockIdx.x == 0) {
        if (t < BITD) g_SUpad[t * 16] = 0.0;
        if (t == 0) { g_SUsq = 0.0; g_corr = 0.0; g_done = 0u; }
    }
    __syncthreads();

    float2 v = ((const float2*)(u + row * BITD))[lane];
    float usq = v.x * v.x + v.y * v.y;
    float s2  = ((v.x > 0.f) ? 0.f : ((v.x < 0.f) ? 2.f : 1.f))
              + ((v.y > 0.f) ? 0.f : ((v.y < 0.f) ? 2.f : 1.f));
    atomicAdd(&scol[2 * lane],     v.x);
    atomicAdd(&scol[2 * lane + 1], v.y);
    float usqr = wred(usq);
    float s2r  = wred(s2);
    if (lane == 0) { g_usq[row] = usqr; sv[warp] = usqr; sv[4 + warp] = s2r; }

    uint4 b = pack_ballots(y + (size_t)row * NCLS, lane);
    if (lane == 0) {
        g_ypk[row]             = b.x;
        g_ypk[BATCH + row]     = b.y;
        g_ypk[2 * BATCH + row] = b.z;
        g_ypk[3 * BATCH + row] = b.w;
    }
    __syncthreads();

    if (t < BITD) g_supart[blockIdx.x * BITD + t] = scol[t];
    if (t == 0) {
        g_uqpart[blockIdx.x] = sv[0] + sv[1] + sv[2] + sv[3];
        g_s2part[blockIdx.x] = sv[4] + sv[5] + sv[6] + sv[7];
    }
}

// ------------- pack kernel: pure Y -> packed-bit stream ------------------
// warp packs 16 rows: 2 rounds of 8 batched (guarded) float4 loads + ballots.
__global__ void __launch_bounds__(256)
k_pack(const float* __restrict__ Y) {
    int lane  = threadIdx.x & 31;
    int gw    = blockIdx.x * 8 + (threadIdx.x >> 5);
    int rbase = gw * 16;

#pragma unroll
    for (int r0 = 0; r0 < 16; r0 += 8) {
        float4 vv[8];
#pragma unroll
        for (int j = 0; j < 8; j++) {
            int nr = rbase + r0 + j;
            if (nr >= NTRAIN) nr = NTRAIN - 1;
            vv[j] = make_float4(0.f, 0.f, 0.f, 0.f);
            if (lane < 25)
                vv[j] = ((const float4*)(Y + (size_t)nr * NCLS))[lane];
        }
#pragma unroll
        for (int j = 0; j < 8; j++) {
            uint4 b = pack_ballots_v(vv[j]);
            int nr = rbase + r0 + j;
            if (lane == 0 && nr < NTRAIN) g_ypkN[nr] = b;
        }
    }
}

// ------------- mega kernel: scan + U-stats + fix + finalize tail ---------
__global__ void __launch_bounds__(256)
k_mega(const float* __restrict__ u, const int* __restrict__ ind,
       const float* __restrict__ U, const float* __restrict__ Y,
       float* __restrict__ out) {
    __shared__ __align__(16) unsigned sh[4 * BATCH];  // 8KB
    __shared__ int      sind[BATCH];
    __shared__ float    scol[BITD + 8];
    __shared__ unsigned yn4[4];
    __shared__ int      s_last;
    __shared__ int      s_flag;

    int t    = threadIdx.x;
    int lane = t & 31, warp = t >> 5;

    if (blockIdx.x < SCAN_BLOCKS) {
        // ================= scan role =====================================
#pragma unroll
        for (int i = 0; i < 2; i++)
            ((uint4*)sh)[t + i * 256] = ((const uint4*)g_ypk)[t + i * 256];

        int n = blockIdx.x * 256 + t;
        uint4 pk = make_uint4(0u, 0u, 0u, 0u);
        if (n < NTRAIN) pk = g_ypkN[n];           // 1 coalesced LDG.128
        unsigned w0 = pk.x, w1 = pk.y, w2 = pk.z, w3 = pk.w;
        __syncthreads();

        if (n < NTRAIN) {
            const uint4* sh4 = (const uint4*)sh;  // word-0 table as uint4
            double corr = 0.0;
#pragma unroll 4
            for (int b0i = 0; b0i < BATCH; b0i += 8) {
                uint4 pa = sh4[b0i >> 2];
                uint4 pb = sh4[(b0i >> 2) + 1];
                unsigned mna = min(min(pa.x & w0, pa.y & w0),
                                   min(pa.z & w0, pa.w & w0));
                unsigned mnb = min(min(pb.x & w0, pb.y & w0),
                                   min(pb.z & w0, pb.w & w0));
                if (min(mna, mnb) == 0u) {
#pragma unroll 1
                    for (int j = 0; j < 8; j++) {
                        int b = b0i + j;
                        unsigned r = (sh[b] & w0) | (sh[BATCH + b] & w1) |
                                     (sh[2 * BATCH + b] & w2) |
                                     (sh[3 * BATCH + b] & w3);
                        if (r == 0u)
                            corr += pair_term(b, u + b * BITD,
                                              U + (size_t)n * BITD);
                    }
                }
            }
            if (corr != 0.0) atomicAdd(&g_corr, corr);
        }
    } else if (blockIdx.x < SCAN_BLOCKS + UST_BLOCKS) {
        // ================= U stats role ==================================
        const int nth = UST_BLOCKS * 256;                 // 131072
        int gid = (blockIdx.x - SCAN_BLOCKS) * 256 + t;
        const float4* U4 = (const float4*)U;
        const int total4 = NTRAIN * BITD / 4;             // 1.6M

        float c0 = 0.f, c1 = 0.f, c2 = 0.f, c3 = 0.f, sq = 0.f;
#pragma unroll 4
        for (int i = gid; i < total4; i += nth) {
            float4 v = U4[i];
            c0 += v.x; c1 += v.y; c2 += v.z; c3 += v.w;
            sq += v.x * v.x + v.y * v.y + v.z * v.z + v.w * v.w;
        }
        int cbase = (4 * gid) & (BITD - 1);
        c0 += __shfl_xor_sync(0xffffffffu, c0, 16);
        c1 += __shfl_xor_sync(0xffffffffu, c1, 16);
        c2 += __shfl_xor_sync(0xffffffffu, c2, 16);
        c3 += __shfl_xor_sync(0xffffffffu, c3, 16);
        sq = wred(sq);

        if (t < BITD + 8) scol[t] = 0.f;
        __syncthreads();
        if (lane < 16) {
            atomicAdd(&scol[cbase],     c0);
            atomicAdd(&scol[cbase + 1], c1);
            atomicAdd(&scol[cbase + 2], c2);
            atomicAdd(&scol[cbase + 3], c3);
        }
        if (lane == 0) scol[BITD + warp] = sq;
        __syncthreads();
        if (t < BITD) atomicAdd(&g_SUpad[t * 16], (double)scol[t]);
        if (t == 0) {
            float s = 0.f;
#pragma unroll
            for (int w = 0; w < 8; w++) s += scol[BITD + w];
            atomicAdd(&g_SUsq, (double)s);
        }
    } else {
        // ================= fix role: one block per batch row =============
        int i = blockIdx.x - SCAN_BLOCKS - UST_BLOCKS;    // 0..511

        sind[t]       = ind[t];
        sind[t + 256] = ind[t + 256];
#pragma unroll
        for (int j = 0; j < 2; j++)
            ((uint4*)sh)[t + j * 256] = ((const uint4*)g_ypk)[t + j * 256];
        if (t == 0) s_last = 1;
        __syncthreads();

        int n = sind[i];
        for (int j = i + 1 + t; j < BATCH; j += 256)
            if (sind[j] == n) s_last = 0;
        __syncthreads();

        if (s_last) {
            if (t == 0) {
                uint4 b = g_ypkN[n];              // packed original Y row n
                yn4[0] = b.x; yn4[1] = b.y; yn4[2] = b.z; yn4[3] = b.w;
            }
            __syncthreads();

            unsigned yn0 = yn4[0], yn1 = yn4[1], yn2 = yn4[2], yn3 = yn4[3];
            unsigned m0 = sh[i],             m1 = sh[BATCH + i];
            unsigned m2 = sh[2 * BATCH + i], m3 = sh[3 * BATCH + i];
            double corr = 0.0;
#pragma unroll
            for (int bb = 0; bb < 2; bb++) {
                int b = t + bb * 256;
                unsigned ro = (sh[b] & yn0) | (sh[BATCH + b] & yn1) |
                              (sh[2 * BATCH + b] & yn2) |
                              (sh[3 * BATCH + b] & yn3);
                if (ro == 0u)   // remove scan's old-data contribution
                    corr -= pair_term(b, u + b * BITD, U + (size_t)n * BITD);
                unsigned rn = (sh[b] & m0) | (sh[BATCH + b] & m1) |
                              (sh[2 * BATCH + b] & m2) |
                              (sh[3 * BATCH + b] & m3);
                if (rn == 0u)   // add updated-data contribution
                    corr += pair_term(b, u + b * BITD, u + i * BITD);
            }
            if (corr != 0.0) atomicAdd(&g_corr, corr);

            float dsq = 0.f;
            if (t < BITD) {
                float a = u[i * BITD + t];
                float c = U[(size_t)n * BITD + t];
                atomicAdd(&g_SUpad[t * 16], (double)(a - c));
                dsq = a * a - c * c;
                dsq = wred(dsq);
                if (lane == 0) atomicAdd(&g_SUsq, (double)dsq);
            }
        }
    }

    // ================= finalize tail: last block to finish ===============
    __threadfence();
    __syncthreads();
    if (t == 0)
        s_flag = (atomicAdd(&g_done, 1u) == MEGA_BLOCKS - 1) ? 1 : 0;
    __syncthreads();
    if (!s_flag) return;
    __threadfence();

    __shared__ double sterm[BITD];
    __shared__ double sparts[8];

    if (t < BITD) {
        double s = 0.0;
#pragma unroll 8
        for (int i = 0; i < BATCH_BLOCKS; i++)
            s += (double)g_supart[i * BITD + t];
        sterm[t] = s * g_SUpad[t * 16];
    }
    if (t < BATCH_BLOCKS) {
        double q = wredd((double)g_uqpart[t]);
        double a = wredd((double)g_s2part[t]);
        if (lane == 0) { sparts[warp] = q; sparts[4 + warp] = a; }
    }
    __syncthreads();

    if (t == 0) {
        double dotsum = 0.0;
#pragma unroll
        for (int k = 0; k < BITD; k++) dotsum += sterm[k];
        double sum_usq = sparts[0] + sparts[1] + sparts[2] + sparts[3];
        double s2sum   = sparts[4] + sparts[5] + sparts[6] + sparts[7];
        double sum_dist = (double)NTRAIN * sum_usq
                        + (double)BATCH  * g_SUsq
                        - 2.0 * dotsum;
        double loss1 = (0.5 * sum_dist + g_corr)
                     / ((double)BATCH * (double)NTRAIN);
        double loss2 = 0.1 * s2sum / ((double)BATCH * (double)BITD);
        out[0] = (float)(loss1 + loss2);
    }
}

// ------------------------------------------------------------ launcher
extern "C" void kernel_launch(void* const* d_in, const int* in_sizes, int n_in,
                              void* d_out, int out_size) {
    const float* u   = (const float*)d_in[0];   // [512, 64]
    const float* y   = (const float*)d_in[1];   // [512, 100]
    const int*   ind = (const int*)  d_in[2];   // [512]
    const float* U   = (const float*)d_in[3];   // [100000, 64]
    const float* Y   = (const float*)d_in[4];   // [100000, 100]
    float* out = (float*)d_out;

    k_batch<<<BATCH_BLOCKS, 256>>>(u, y);
    k_pack<<<PACK_BLOCKS, 256>>>(Y);
    k_mega<<<MEGA_BLOCKS, 256>>>(u, ind, U, Y, out);
}